// round 6
// baseline (speedup 1.0000x reference)
#include <cuda_runtime.h>
#include <cuda_bf16.h>

// Shapes (fixed): B=2, N=2048, K=48, A=4
// X: (B,N,4,3) f32; edge_idx: (B,N,48) i32; C: (B,N) i32
// out: (B,N,48,192) f32
//
// R = Q*diag(s): Q orthonormal (exact), s_y = ||n_y||. Rotate atoms once by
// Q^T (norm-preserving), then each pair is diff + rsqrt + per-axis (mask*s_y).
//
// smem layout: sA[k][32] floats (128B pitch), atom a at float 4a (one aligned
// LDS.128 per atom). sMS[k] = float4(mk*s1, mk*s2, mk*s3, 0) pre-folded.
// Thread t writes output float4 f = t + 384q: coalesced STG.128; r = f%48
// loop-invariant, so all pair/index math hoisted.

#define BB 2
#define NN 2048
#define KK 48
#define EPS 0.1f
#define THREADS 384
#define ROWF 32                  // padded floats per k row (128 B)
#define KSTRIDE (8 * ROWF)       // k advances by 8 per q

__global__ __launch_bounds__(THREADS) void edge_orient_kernel(
    const float* __restrict__ X,
    const int*   __restrict__ E,
    const int*   __restrict__ C,
    float*       __restrict__ out)
{
    const int bn = blockIdx.x;
    const int b  = bn >> 11;          // / NN
    const int t  = threadIdx.x;

    __shared__ __align__(16) float  sA[KK][ROWF];   // Q^T-rotated, padded
    __shared__ __align__(16) float4 sMS[KK];        // mask*scales per k
    __shared__ int   sJ[KK];
    __shared__ float sR[9];
    __shared__ float sS[3];

    const int* e_row = E + (size_t)bn * KK;

    // ---- phase 1: neighbor indices + frame ----
    if (t < KK) sJ[t] = e_row[t];
    if (t == 64) {
        const float* xr = X + (size_t)bn * 12;
        float Nx = xr[0], Ny = xr[1], Nz = xr[2];
        float Ax = xr[3], Ay = xr[4], Az = xr[5];
        float Cx = xr[6], Cy = xr[7], Cz = xr[8];

        float ux = Nx - Ax, uy = Ny - Ay, uz = Nz - Az;
        float invE = rsqrtf(ux*ux + uy*uy + uz*uz + EPS);
        float n1x = ux*invE, n1y = uy*invE, n1z = uz*invE;
        float n1n2 = n1x*n1x + n1y*n1y + n1z*n1z;
        float inv0 = rsqrtf(n1n2);
        float q1x = n1x*inv0, q1y = n1y*inv0, q1z = n1z*inv0;
        float s1  = n1n2 * inv0;

        float vx = Cx - Ax, vy = Cy - Ay, vz = Cz - Az;
        float invV = rsqrtf(vx*vx + vy*vy + vz*vz + EPS);
        vx *= invV; vy *= invV; vz *= invV;

        float c2x = n1y*vz - n1z*vy;
        float c2y = n1z*vx - n1x*vz;
        float c2z = n1x*vy - n1y*vx;
        invE = rsqrtf(c2x*c2x + c2y*c2y + c2z*c2z + EPS);
        float n2x = c2x*invE, n2y = c2y*invE, n2z = c2z*invE;
        float n2n2 = n2x*n2x + n2y*n2y + n2z*n2z;
        inv0 = rsqrtf(n2n2);
        float q2x = n2x*inv0, q2y = n2y*inv0, q2z = n2z*inv0;
        float s2  = n2n2 * inv0;

        float c3x = n1y*n2z - n1z*n2y;
        float c3y = n1z*n2x - n1x*n2z;
        float c3z = n1x*n2y - n1y*n2x;
        invE = rsqrtf(c3x*c3x + c3y*c3y + c3z*c3z + EPS);
        float n3x = c3x*invE, n3y = c3y*invE, n3z = c3z*invE;
        float n3n2 = n3x*n3x + n3y*n3y + n3z*n3z;
        inv0 = rsqrtf(n3n2);

        sR[0] = q1x;      sR[1] = q1y;      sR[2] = q1z;
        sR[3] = q2x;      sR[4] = q2y;      sR[5] = q2z;
        sR[6] = n3x*inv0; sR[7] = n3y*inv0; sR[8] = n3z*inv0;
        sS[0] = s1; sS[1] = s2; sS[2] = n3n2 * inv0;
    }
    __syncthreads();

    // ---- phase 2: rotate atoms from global into padded smem; fold mask*s ----
    {
        const int k = t >> 3;
        const int a = t & 7;
        const int j = sJ[k];
        const float* src = (a < 4)
            ? (X + (size_t)bn * 12 + 3 * a)
            : (X + ((size_t)(b * NN + j)) * 12 + 3 * (a - 4));
        const float x = src[0], y = src[1], z = src[2];
        const float rx = x*sR[0] + y*sR[1] + z*sR[2];
        const float ry = x*sR[3] + y*sR[4] + z*sR[5];
        const float rz = x*sR[6] + y*sR[7] + z*sR[8];
        *(float4*)&sA[k][4 * a] = make_float4(rx, ry, rz, 0.0f);

        if (a == 0) {
            const float mk = ((C[bn] > 0) && (C[b * NN + j] > 0)) ? 1.0f : 0.0f;
            sMS[k] = make_float4(mk * sS[0], mk * sS[1], mk * sS[2], 0.0f);
        }
    }
    __syncthreads();

    // ---- phase 3: outputs ----
    const int k0 = t / 48;
    const int r  = t - k0 * 48;       // loop-invariant
    const int fr = 4 * r;
    const int s0 = fr / 3;
    const int c0 = fr - s0 * 3;
    const int s1i = s0 + 1;

    const int a0 = (s0  >> 3), b0 = (s0  & 7);
    const int a1 = (s1i >> 3), b1 = (s1i & 7);
    const bool sameA = (a1 == a0);

    const float4* pA0 = (const float4*)&sA[k0][4 * a0];
    const float4* pB0 = (const float4*)&sA[k0][4 * b0];
    const float4* pA1 = (const float4*)&sA[k0][4 * a1];
    const float4* pB1 = (const float4*)&sA[k0][4 * b1];
    const float4* pM  = &sMS[k0];

    float4* op = (float4*)(out + (size_t)bn * (KK * 192)) + t;

#pragma unroll
    for (int q = 0; q < 6; q++) {
        const float4 ms = *pM;
        const float4 A0 = *pA0;
        const float4 B0 = *pB0;
        const float4 B1 = *pB1;
        const float4 A1 = sameA ? A0 : *pA1;

        float v0x, v0y, v0z, v1x, v1y, v1z;
        {
            const float dx = B0.x - A0.x;
            const float dy = B0.y - A0.y;
            const float dz = B0.z - A0.z;
            const float inv = rsqrtf(dx*dx + dy*dy + dz*dz + EPS);
            v0x = dx * inv * ms.x; v0y = dy * inv * ms.y; v0z = dz * inv * ms.z;
        }
        {
            const float dx = B1.x - A1.x;
            const float dy = B1.y - A1.y;
            const float dz = B1.z - A1.z;
            const float inv = rsqrtf(dx*dx + dy*dy + dz*dz + EPS);
            v1x = dx * inv * ms.x; v1y = dy * inv * ms.y; v1z = dz * inv * ms.z;
        }

        float4 o;
        if (c0 == 0)      { o.x = v0x; o.y = v0y; o.z = v0z; o.w = v1x; }
        else if (c0 == 1) { o.x = v0y; o.y = v0z; o.z = v1x; o.w = v1y; }
        else              { o.x = v0z; o.y = v1x; o.z = v1y; o.w = v1z; }
        *op = o;

        pA0 += KSTRIDE / 4; pB0 += KSTRIDE / 4;
        pA1 += KSTRIDE / 4; pB1 += KSTRIDE / 4;
        pM  += 8;
        op  += THREADS;
    }
}

extern "C" void kernel_launch(void* const* d_in, const int* in_sizes, int n_in,
                              void* d_out, int out_size) {
    const float* X = (const float*)d_in[0];
    const int*   E = (const int*)d_in[1];
    const int*   C = (const int*)d_in[2];
    float* out = (float*)d_out;

    edge_orient_kernel<<<BB * NN, THREADS>>>(X, E, C, out);
}